// round 3
// baseline (speedup 1.0000x reference)
#include <cuda_runtime.h>
#include <cuda_fp16.h>

// Problem constants
#define BATCH 2
#define SEQL  2048
#define NH    32
#define NKV   8
#define HD    128
#define NGL   32             // pseudo-head groups per batch (L*H / L)
#define KVD   512            // distinct KV rows per pseudo-batch

// Tile config
#define BM 64                // query rows per CTA
#define BN 64                // distinct kv rows per tile
#define NTHREADS 256
#define QK_STRIDE 129
#define S_STRIDE  65

__global__ __launch_bounds__(NTHREADS, 1)
void attn_flash_kernel(const float* __restrict__ Qg,
                       const float* __restrict__ Kg,
                       const float* __restrict__ Vg,
                       float* __restrict__ Og)
{
    extern __shared__ float sm[];
    float* sQ = sm;                               // BM x QK_STRIDE
    float* sK = sQ + BM * QK_STRIDE;              // BN x QK_STRIDE
    float* sV = sK + BN * QK_STRIDE;              // BN x QK_STRIDE
    float* sS = sV + BN * QK_STRIDE;              // BM x S_STRIDE
    float* sM = sS + BM * S_STRIDE;
    float* sL = sM + BM;
    float* sC = sL + BM;

    const int q0  = blockIdx.x * BM;              // query-row tile within pseudo-batch
    const int pb  = blockIdx.y;                   // pseudo-batch: b*32 + gl
    const int b   = pb >> 5;
    const int gl  = pb & 31;
    const int tid = threadIdx.x;
    const int ty  = tid >> 4;                     // 0..15
    const int tx  = tid & 15;                     // 0..15

    const float scale = __half2float(__float2half(0.08838834764831845f));

    // ---- load Q tile: row r -> Q[b, gl*64 + (r>>5), h=r&31, :] ----
    for (int i = tid; i < BM * HD; i += NTHREADS) {
        const int rr = i >> 7;                    // 0..63 local row
        const int d  = i & 127;
        const int r  = q0 + rr;                   // global pseudo row
        const int l  = gl * 64 + (r >> 5);
        const int h  = r & 31;
        const float g = Qg[(((size_t)b * SEQL + l) * NH + h) * HD + d];
        sQ[rr * QK_STRIDE + d] = __half2float(__float2half(g));
    }
    if (tid < BM) { sM[tid] = -1e30f; sL[tid] = 0.0f; }

    float acc[4][8];
    #pragma unroll
    for (int i = 0; i < 4; i++)
        #pragma unroll
        for (int j = 0; j < 8; j++) acc[i][j] = 0.0f;

    for (int kv0 = 0; kv0 < KVD; kv0 += BN) {
        __syncthreads();
        // ---- load distinct K/V tile: g -> K[b, gl*64 + (g>>3), kh=g&7, :] ----
        for (int i = tid; i < BN * HD; i += NTHREADS) {
            const int rr = i >> 7;
            const int d  = i & 127;
            const int g  = kv0 + rr;
            const int l  = gl * 64 + (g >> 3);
            const int kh = g & 7;
            const size_t gi = (((size_t)b * SEQL + l) * NKV + kh) * HD + d;
            sK[rr * QK_STRIDE + d] = __half2float(__float2half(Kg[gi]));
            sV[rr * QK_STRIDE + d] = __half2float(__float2half(Vg[gi]));
        }
        __syncthreads();

        // ---- S = (Q K^T) * scale, rounded through fp16 ----
        float s[4][4];
        #pragma unroll
        for (int i = 0; i < 4; i++)
            #pragma unroll
            for (int j = 0; j < 4; j++) s[i][j] = 0.0f;

        #pragma unroll 4
        for (int d = 0; d < HD; d++) {
            float qv[4], kv[4];
            #pragma unroll
            for (int i = 0; i < 4; i++) qv[i] = sQ[(ty * 4 + i) * QK_STRIDE + d];
            #pragma unroll
            for (int j = 0; j < 4; j++) kv[j] = sK[(tx * 4 + j) * QK_STRIDE + d];
            #pragma unroll
            for (int i = 0; i < 4; i++)
                #pragma unroll
                for (int j = 0; j < 4; j++)
                    s[i][j] = fmaf(qv[i], kv[j], s[i][j]);
        }
        #pragma unroll
        for (int i = 0; i < 4; i++)
            #pragma unroll
            for (int j = 0; j < 4; j++)
                sS[(ty * 4 + i) * S_STRIDE + (tx * 4 + j)] =
                    __half2float(__float2half(s[i][j] * scale));
        __syncthreads();

        // ---- online softmax (distinct cols; 4x duplication cancels) ----
        if (tid < BM) {
            const int r = tid;
            const float mOld = sM[r];
            float mx = mOld;
            #pragma unroll 8
            for (int c = 0; c < BN; c++) mx = fmaxf(mx, sS[r * S_STRIDE + c]);
            const float corr = __expf(mOld - mx);
            float sum = 0.0f;
            #pragma unroll 8
            for (int c = 0; c < BN; c++) {
                const float p = __expf(sS[r * S_STRIDE + c] - mx);
                sS[r * S_STRIDE + c] = p;
                sum += p;
            }
            sM[r] = mx;
            sL[r] = sL[r] * corr + sum;
            sC[r] = corr;
        }
        __syncthreads();

        // ---- rescale O and accumulate P*V ----
        #pragma unroll
        for (int i = 0; i < 4; i++) {
            const float c = sC[ty * 4 + i];
            #pragma unroll
            for (int j = 0; j < 8; j++) acc[i][j] *= c;
        }
        #pragma unroll 2
        for (int k = 0; k < BN; k++) {
            float p[4], v[8];
            #pragma unroll
            for (int i = 0; i < 4; i++) p[i] = sS[(ty * 4 + i) * S_STRIDE + k];
            #pragma unroll
            for (int j = 0; j < 8; j++) v[j] = sV[k * QK_STRIDE + tx * 8 + j];
            #pragma unroll
            for (int i = 0; i < 4; i++)
                #pragma unroll
                for (int j = 0; j < 8; j++)
                    acc[i][j] = fmaf(p[i], v[j], acc[i][j]);
        }
    }
    __syncthreads();

    // ---- normalize and store: row r -> Og[b, r, gl*128 + d] (fp32 out) ----
    #pragma unroll
    for (int i = 0; i < 4; i++) {
        const int rr = ty * 4 + i;
        const int r  = q0 + rr;
        const float inv = 1.0f / sL[rr];
        const size_t base = (((size_t)b * SEQL + r) * NH + gl) * HD + tx * 8;
        #pragma unroll
        for (int j = 0; j < 8; j++)
            Og[base + j] = acc[i][j] * inv;
    }
}

extern "C" void kernel_launch(void* const* d_in, const int* in_sizes, int n_in,
                              void* d_out, int out_size)
{
    const float* Q = (const float*)d_in[0];
    const float* K = (const float*)d_in[1];
    const float* V = (const float*)d_in[2];
    float* O = (float*)d_out;

    const int smem_bytes = (3 * BM * QK_STRIDE + BM * S_STRIDE + 3 * BM) * (int)sizeof(float);
    cudaFuncSetAttribute(attn_flash_kernel,
                         cudaFuncAttributeMaxDynamicSharedMemorySize, smem_bytes);

    dim3 grid(SEQL / BM, BATCH * NGL);
    attn_flash_kernel<<<grid, NTHREADS, smem_bytes>>>(Q, K, V, O);
}

// round 4
// speedup vs baseline: 4.6598x; 4.6598x over previous
#include <cuda_runtime.h>
#include <cuda_fp16.h>
#include <cstdint>

#define BATCH 2
#define SEQL  2048
#define NH    32
#define NKV   8
#define HD    128
#define KVD   512            // distinct KV rows per pseudo-batch

#define BM 128               // query rows per CTA
#define BN 64                // kv rows per tile
#define NWARP 8
#define NTHREADS 256

#define SK_STRIDE  136       // halves per K-tile row
#define SVT_STRIDE 72        // halves per Vt row (HD rows x BN cols)
#define SP_STRIDE  72        // halves per P row
#define SS_STRIDE  65        // floats per S row

// fp32 -> packed half2 (lo = a, hi = b)
__device__ __forceinline__ uint32_t pack_h2(float a, float b) {
    __half2 h = __floats2half2_rn(a, b);
    return *reinterpret_cast<uint32_t*>(&h);
}

__device__ __forceinline__ void mma16816(float c[4], const uint32_t a[4],
                                         uint32_t b0, uint32_t b1) {
    asm volatile(
        "mma.sync.aligned.m16n8k16.row.col.f32.f16.f16.f32 "
        "{%0,%1,%2,%3}, {%4,%5,%6,%7}, {%8,%9}, {%0,%1,%2,%3};\n"
        : "+f"(c[0]), "+f"(c[1]), "+f"(c[2]), "+f"(c[3])
        : "r"(a[0]), "r"(a[1]), "r"(a[2]), "r"(a[3]), "r"(b0), "r"(b1));
}

// accurate exp on FMA pipe: exp(x) = 2^(x*log2e), deg-5 poly, rel err ~2e-6
__device__ __forceinline__ float fast_exp(float x) {
    float y = x * 1.4426950408889634f;
    y = fmaxf(y, -126.0f);
    float t  = y + 12582912.0f;             // 1.5 * 2^23 round-to-int magic
    float ri = t - 12582912.0f;
    float f  = y - ri;
    int iexp = __float_as_int(t) - 0x4B400000;
    float scale = __int_as_float((iexp + 127) << 23);
    float p = 0.0013333558f;
    p = fmaf(p, f, 0.0096181291f);
    p = fmaf(p, f, 0.0555041087f);
    p = fmaf(p, f, 0.2402265069f);
    p = fmaf(p, f, 0.6931471806f);
    p = fmaf(p, f, 1.0f);
    return p * scale;
}

__global__ __launch_bounds__(NTHREADS, 1)
void attn_hmma_kernel(const float* __restrict__ Qg,
                      const float* __restrict__ Kg,
                      const float* __restrict__ Vg,
                      float* __restrict__ Og)
{
    extern __shared__ char smem_raw[];
    __half* sK  = reinterpret_cast<__half*>(smem_raw);            // BN x SK_STRIDE
    __half* sVt = sK  + BN * SK_STRIDE;                           // HD x SVT_STRIDE
    __half* sP  = sVt + HD * SVT_STRIDE;                          // BM x SP_STRIDE
    float*  sS  = reinterpret_cast<float*>(sP + BM * SP_STRIDE);  // BM x SS_STRIDE
    float*  sM  = sS + BM * SS_STRIDE;
    float*  sL  = sM + BM;
    float*  sC  = sL + BM;

    const int pb = blockIdx.y;           // pseudo-batch = b*32 + gl
    const int b  = pb >> 5;
    const int gl = pb & 31;
    const int q0 = blockIdx.x * BM;
    const int tid  = threadIdx.x;
    const int wid  = tid >> 5;
    const int lane = tid & 31;
    const int g = lane >> 2;             // fragment row group 0..7
    const int t = lane & 3;              // fragment col group 0..3

    // contiguous pseudo-matrices
    const size_t qbase  = ((size_t)b * SEQL + (size_t)gl * 64) * NH  * HD;
    const size_t kvbase = ((size_t)b * SEQL + (size_t)gl * 64) * NKV * HD;

    const __half hscale = __float2half(0.08838834764831845f);

    // ---- Q A-fragments in registers for the whole kernel (fp32 -> fp16) ----
    uint32_t qa[8][4];
    {
        const float* q_r0 = Qg + qbase + (size_t)(q0 + wid * 16 + g) * HD;
        const float* q_r8 = q_r0 + 8 * HD;
        #pragma unroll
        for (int kt = 0; kt < 8; kt++) {
            const int c0 = kt * 16 + t * 2;
            float2 a0 = *reinterpret_cast<const float2*>(q_r0 + c0);
            float2 a1 = *reinterpret_cast<const float2*>(q_r8 + c0);
            float2 a2 = *reinterpret_cast<const float2*>(q_r0 + c0 + 8);
            float2 a3 = *reinterpret_cast<const float2*>(q_r8 + c0 + 8);
            qa[kt][0] = pack_h2(a0.x, a0.y);
            qa[kt][1] = pack_h2(a1.x, a1.y);
            qa[kt][2] = pack_h2(a2.x, a2.y);
            qa[kt][3] = pack_h2(a3.x, a3.y);
        }
    }

    if (tid < BM) { sM[tid] = -1e30f; sL[tid] = 0.0f; }

    float o[16][4];
    #pragma unroll
    for (int d = 0; d < 16; d++)
        #pragma unroll
        for (int j = 0; j < 4; j++) o[d][j] = 0.0f;

    for (int kv0 = 0; kv0 < KVD; kv0 += BN) {
        __syncthreads();   // previous tile's PV done before overwriting tiles

        // ---- load K tile row-major fp16 ----
        for (int i = tid; i < BN * 32; i += NTHREADS) {
            const int r  = i >> 5;
            const int c4 = i & 31;
            float4 v = *reinterpret_cast<const float4*>(
                Kg + kvbase + (size_t)(kv0 + r) * HD + c4 * 4);
            uint2 packed;
            packed.x = pack_h2(v.x, v.y);
            packed.y = pack_h2(v.z, v.w);
            *reinterpret_cast<uint2*>(sK + r * SK_STRIDE + c4 * 4) = packed;
        }
        // ---- load V transposed: sVt[d][g] (half2 pairs along seq) ----
        for (int i = tid; i < (BN / 2) * 32; i += NTHREADS) {
            const int gp = i & 31;        // seq pair index (rows 2gp, 2gp+1)
            const int c4 = i >> 5;        // d block of 4
            const float* v0 = Vg + kvbase + (size_t)(kv0 + 2 * gp) * HD + c4 * 4;
            float4 va = *reinterpret_cast<const float4*>(v0);
            float4 vb = *reinterpret_cast<const float4*>(v0 + HD);
            const float* pa = &va.x;
            const float* pb2 = &vb.x;
            #pragma unroll
            for (int j = 0; j < 4; j++) {
                *reinterpret_cast<uint32_t*>(sVt + (c4 * 4 + j) * SVT_STRIDE + 2 * gp)
                    = pack_h2(pa[j], pb2[j]);
            }
        }
        __syncthreads();

        // ---- S = Q K^T (HMMA) ----
        {
            float sc[8][4];
            #pragma unroll
            for (int nt = 0; nt < 8; nt++) {
                #pragma unroll
                for (int j = 0; j < 4; j++) sc[nt][j] = 0.0f;
            }
            #pragma unroll
            for (int kt = 0; kt < 8; kt++) {
                #pragma unroll
                for (int nt = 0; nt < 8; nt++) {
                    const __half* kp = sK + (nt * 8 + g) * SK_STRIDE + kt * 16 + 2 * t;
                    uint32_t b0 = *reinterpret_cast<const uint32_t*>(kp);
                    uint32_t b1 = *reinterpret_cast<const uint32_t*>(kp + 8);
                    mma16816(sc[nt], qa[kt], b0, b1);
                }
            }
            // write S with reference-exact double fp16 rounding
            const int r0 = wid * 16 + g;
            #pragma unroll
            for (int nt = 0; nt < 8; nt++) {
                const int n0 = nt * 8 + 2 * t;
                sS[r0 * SS_STRIDE + n0]           = __half2float(__hmul(__float2half(sc[nt][0]), hscale));
                sS[r0 * SS_STRIDE + n0 + 1]       = __half2float(__hmul(__float2half(sc[nt][1]), hscale));
                sS[(r0 + 8) * SS_STRIDE + n0]     = __half2float(__hmul(__float2half(sc[nt][2]), hscale));
                sS[(r0 + 8) * SS_STRIDE + n0 + 1] = __half2float(__hmul(__float2half(sc[nt][3]), hscale));
            }
        }
        __syncthreads();

        // ---- online softmax: one thread per row ----
        if (tid < BM) {
            const int r = tid;
            const float mOld = sM[r];
            float mx = mOld;
            #pragma unroll 8
            for (int c = 0; c < BN; c++) mx = fmaxf(mx, sS[r * SS_STRIDE + c]);
            const float corr = fast_exp(mOld - mx);
            float sum = 0.0f;
            #pragma unroll 4
            for (int c = 0; c < BN; c += 2) {
                const float p0 = fast_exp(sS[r * SS_STRIDE + c]     - mx);
                const float p1 = fast_exp(sS[r * SS_STRIDE + c + 1] - mx);
                const __half h0 = __float2half(p0);
                const __half h1 = __float2half(p1);
                *reinterpret_cast<__half2*>(sP + r * SP_STRIDE + c) = __halves2half2(h0, h1);
                sum += __half2float(h0) + __half2float(h1);
            }
            sM[r] = mx;
            sL[r] = sL[r] * corr + sum;
            sC[r] = corr;
        }
        __syncthreads();

        // ---- rescale O by correction factor ----
        {
            const float cr0 = sC[wid * 16 + g];
            const float cr1 = sC[wid * 16 + g + 8];
            #pragma unroll
            for (int dt = 0; dt < 16; dt++) {
                o[dt][0] *= cr0; o[dt][1] *= cr0;
                o[dt][2] *= cr1; o[dt][3] *= cr1;
            }
        }

        // ---- O += P V (HMMA) ----
        #pragma unroll
        for (int kt = 0; kt < 4; kt++) {
            uint32_t pa[4];
            const __half* pp = sP + (wid * 16 + g) * SP_STRIDE + kt * 16 + 2 * t;
            pa[0] = *reinterpret_cast<const uint32_t*>(pp);
            pa[1] = *reinterpret_cast<const uint32_t*>(pp + 8 * SP_STRIDE);
            pa[2] = *reinterpret_cast<const uint32_t*>(pp + 8);
            pa[3] = *reinterpret_cast<const uint32_t*>(pp + 8 * SP_STRIDE + 8);
            #pragma unroll
            for (int dt = 0; dt < 16; dt++) {
                const __half* vp = sVt + (dt * 8 + g) * SVT_STRIDE + kt * 16 + 2 * t;
                uint32_t b0 = *reinterpret_cast<const uint32_t*>(vp);
                uint32_t b1 = *reinterpret_cast<const uint32_t*>(vp + 8);
                mma16816(o[dt], pa, b0, b1);
            }
        }
    }
    __syncthreads();

    // ---- epilogue: normalize, round through fp16, store fp32 ----
    {
        const float il0 = 1.0f / sL[wid * 16 + g];
        const float il1 = 1.0f / sL[wid * 16 + g + 8];
        const size_t r0 = (size_t)q0 + wid * 16 + g;       // pseudo row
        float* out0 = Og + ((size_t)b * SEQL + r0)     * (NH * HD) + gl * HD;
        float* out1 = Og + ((size_t)b * SEQL + r0 + 8) * (NH * HD) + gl * HD;
        #pragma unroll
        for (int dt = 0; dt < 16; dt++) {
            const int d = dt * 8 + 2 * t;
            float2 v0, v1;
            v0.x = __half2float(__float2half(o[dt][0] * il0));
            v0.y = __half2float(__float2half(o[dt][1] * il0));
            v1.x = __half2float(__float2half(o[dt][2] * il1));
            v1.y = __half2float(__float2half(o[dt][3] * il1));
            *reinterpret_cast<float2*>(out0 + d) = v0;
            *reinterpret_cast<float2*>(out1 + d) = v1;
        }
    }
}

extern "C" void kernel_launch(void* const* d_in, const int* in_sizes, int n_in,
                              void* d_out, int out_size)
{
    const float* Q = (const float*)d_in[0];
    const float* K = (const float*)d_in[1];
    const float* V = (const float*)d_in[2];
    float* O = (float*)d_out;

    const int smem_bytes =
        (BN * SK_STRIDE + HD * SVT_STRIDE + BM * SP_STRIDE) * (int)sizeof(__half)
        + (BM * SS_STRIDE + 3 * BM) * (int)sizeof(float);

    cudaFuncSetAttribute(attn_hmma_kernel,
                         cudaFuncAttributeMaxDynamicSharedMemorySize, smem_bytes);

    dim3 grid(SEQL / BM, BATCH * NH);
    attn_hmma_kernel<<<grid, NTHREADS, smem_bytes>>>(Q, K, V, O);
}

// round 5
// speedup vs baseline: 6.2920x; 1.3503x over previous
#include <cuda_runtime.h>
#include <cuda_fp16.h>
#include <cstdint>

#define BATCH 2
#define SEQL  2048
#define NH    32
#define NKV   8
#define HD    128
#define KVD   512            // distinct KV rows per pseudo-batch

#define BM 128               // query rows per CTA
#define BN 64                // kv rows per tile
#define NTHREADS 256

#define SK_STRIDE  136       // halves per K-tile row
#define SVT_STRIDE 72        // halves per Vt row (HD rows x BN cols)

__device__ __forceinline__ uint32_t pack_h2(float a, float b) {
    __half2 h = __floats2half2_rn(a, b);
    return *reinterpret_cast<uint32_t*>(&h);
}

__device__ __forceinline__ void mma16816(float c[4], const uint32_t a[4],
                                         uint32_t b0, uint32_t b1) {
    asm volatile(
        "mma.sync.aligned.m16n8k16.row.col.f32.f16.f16.f32 "
        "{%0,%1,%2,%3}, {%4,%5,%6,%7}, {%8,%9}, {%0,%1,%2,%3};\n"
        : "+f"(c[0]), "+f"(c[1]), "+f"(c[2]), "+f"(c[3])
        : "r"(a[0]), "r"(a[1]), "r"(a[2]), "r"(a[3]), "r"(b0), "r"(b1));
}

// exp on the FMA pipe: exp(x) = 2^(x*log2e), deg-5 poly, rel err ~2e-6
__device__ __forceinline__ float fast_exp(float x) {
    float y = x * 1.4426950408889634f;
    y = fmaxf(y, -126.0f);
    float t  = y + 12582912.0f;
    float ri = t - 12582912.0f;
    float f  = y - ri;
    int iexp = __float_as_int(t) - 0x4B400000;
    float scale = __int_as_float((iexp + 127) << 23);
    float p = 0.0013333558f;
    p = fmaf(p, f, 0.0096181291f);
    p = fmaf(p, f, 0.0555041087f);
    p = fmaf(p, f, 0.2402265069f);
    p = fmaf(p, f, 0.6931471806f);
    p = fmaf(p, f, 1.0f);
    return p * scale;
}

__global__ __launch_bounds__(NTHREADS, 1)
void attn_fa2_kernel(const float* __restrict__ Qg,
                     const float* __restrict__ Kg,
                     const float* __restrict__ Vg,
                     float* __restrict__ Og)
{
    extern __shared__ char smem_raw[];
    __half* sK  = reinterpret_cast<__half*>(smem_raw);   // BN x SK_STRIDE
    __half* sVt = sK + BN * SK_STRIDE;                   // HD x SVT_STRIDE

    const int pb = blockIdx.y;           // pseudo-batch = b*32 + gl
    const int b  = pb >> 5;
    const int gl = pb & 31;
    const int q0 = blockIdx.x * BM;
    const int tid  = threadIdx.x;
    const int wid  = tid >> 5;
    const int lane = tid & 31;
    const int g = lane >> 2;             // fragment row 0..7
    const int t = lane & 3;              // fragment col group 0..3

    const size_t qbase  = ((size_t)b * SEQL + (size_t)gl * 64) * NH  * HD;
    const size_t kvbase = ((size_t)b * SEQL + (size_t)gl * 64) * NKV * HD;

    const __half hscale = __float2half(0.08838834764831845f);

    // ---- Q A-fragments in registers (fp32 -> fp16) ----
    uint32_t qa[8][4];
    {
        const float* q_r0 = Qg + qbase + (size_t)(q0 + wid * 16 + g) * HD;
        const float* q_r8 = q_r0 + 8 * HD;
        #pragma unroll
        for (int kt = 0; kt < 8; kt++) {
            const int c0 = kt * 16 + t * 2;
            float2 a0 = *reinterpret_cast<const float2*>(q_r0 + c0);
            float2 a1 = *reinterpret_cast<const float2*>(q_r8 + c0);
            float2 a2 = *reinterpret_cast<const float2*>(q_r0 + c0 + 8);
            float2 a3 = *reinterpret_cast<const float2*>(q_r8 + c0 + 8);
            qa[kt][0] = pack_h2(a0.x, a0.y);
            qa[kt][1] = pack_h2(a1.x, a1.y);
            qa[kt][2] = pack_h2(a2.x, a2.y);
            qa[kt][3] = pack_h2(a3.x, a3.y);
        }
    }

    // online-softmax state for rows r0 = wid*16+g and r1 = r0+8 (replicated in quad)
    float m0 = -1e30f, m1 = -1e30f;
    float l0 = 0.0f,   l1 = 0.0f;

    float o[16][4];
    #pragma unroll
    for (int d = 0; d < 16; d++)
        #pragma unroll
        for (int j = 0; j < 4; j++) o[d][j] = 0.0f;

    for (int kv0 = 0; kv0 < KVD; kv0 += BN) {
        __syncthreads();   // previous tile's PV done before overwriting sK/sVt

        // ---- load K tile row-major fp16 ----
        for (int i = tid; i < BN * 32; i += NTHREADS) {
            const int r  = i >> 5;
            const int c4 = i & 31;
            float4 v = *reinterpret_cast<const float4*>(
                Kg + kvbase + (size_t)(kv0 + r) * HD + c4 * 4);
            uint2 packed;
            packed.x = pack_h2(v.x, v.y);
            packed.y = pack_h2(v.z, v.w);
            *reinterpret_cast<uint2*>(sK + r * SK_STRIDE + c4 * 4) = packed;
        }
        // ---- load V transposed: sVt[d][seq] ----
        for (int i = tid; i < (BN / 2) * 32; i += NTHREADS) {
            const int gp = i & 31;
            const int c4 = i >> 5;
            const float* v0 = Vg + kvbase + (size_t)(kv0 + 2 * gp) * HD + c4 * 4;
            float4 va = *reinterpret_cast<const float4*>(v0);
            float4 vb = *reinterpret_cast<const float4*>(v0 + HD);
            const float* pa = &va.x;
            const float* pbv = &vb.x;
            #pragma unroll
            for (int j = 0; j < 4; j++) {
                *reinterpret_cast<uint32_t*>(sVt + (c4 * 4 + j) * SVT_STRIDE + 2 * gp)
                    = pack_h2(pa[j], pbv[j]);
            }
        }
        __syncthreads();

        // ---- S = Q K^T (HMMA), kept in registers ----
        float sc[8][4];
        #pragma unroll
        for (int nt = 0; nt < 8; nt++)
            #pragma unroll
            for (int j = 0; j < 4; j++) sc[nt][j] = 0.0f;

        #pragma unroll
        for (int kt = 0; kt < 8; kt++) {
            #pragma unroll
            for (int nt = 0; nt < 8; nt++) {
                const __half* kp = sK + (nt * 8 + g) * SK_STRIDE + kt * 16 + 2 * t;
                uint32_t b0 = *reinterpret_cast<const uint32_t*>(kp);
                uint32_t b1 = *reinterpret_cast<const uint32_t*>(kp + 8);
                mma16816(sc[nt], qa[kt], b0, b1);
            }
        }

        // ---- scale with reference-exact double fp16 rounding (in registers) ----
        #pragma unroll
        for (int nt = 0; nt < 8; nt++) {
            #pragma unroll
            for (int j = 0; j < 4; j++)
                sc[nt][j] = __half2float(__hmul(__float2half(sc[nt][j]), hscale));
        }

        // ---- register softmax: rows r0 (sc[.][0,1]) and r1 (sc[.][2,3]) ----
        float tm0 = -1e30f, tm1 = -1e30f;
        #pragma unroll
        for (int nt = 0; nt < 8; nt++) {
            tm0 = fmaxf(tm0, fmaxf(sc[nt][0], sc[nt][1]));
            tm1 = fmaxf(tm1, fmaxf(sc[nt][2], sc[nt][3]));
        }
        tm0 = fmaxf(tm0, __shfl_xor_sync(0xffffffffu, tm0, 1));
        tm0 = fmaxf(tm0, __shfl_xor_sync(0xffffffffu, tm0, 2));
        tm1 = fmaxf(tm1, __shfl_xor_sync(0xffffffffu, tm1, 1));
        tm1 = fmaxf(tm1, __shfl_xor_sync(0xffffffffu, tm1, 2));

        const float mn0 = fmaxf(m0, tm0);
        const float mn1 = fmaxf(m1, tm1);
        const float cr0 = fast_exp(m0 - mn0);
        const float cr1 = fast_exp(m1 - mn1);
        m0 = mn0; m1 = mn1;

        // exp, round P to fp16 (packed), accumulate fp32 sums of rounded values
        uint32_t ph0[8], ph1[8];
        float sum0 = 0.0f, sum1 = 0.0f;
        #pragma unroll
        for (int nt = 0; nt < 8; nt++) {
            __half2 h0 = __floats2half2_rn(fast_exp(sc[nt][0] - mn0),
                                           fast_exp(sc[nt][1] - mn0));
            __half2 h1 = __floats2half2_rn(fast_exp(sc[nt][2] - mn1),
                                           fast_exp(sc[nt][3] - mn1));
            ph0[nt] = *reinterpret_cast<uint32_t*>(&h0);
            ph1[nt] = *reinterpret_cast<uint32_t*>(&h1);
            float2 f0 = __half22float2(h0);
            float2 f1 = __half22float2(h1);
            sum0 += f0.x + f0.y;
            sum1 += f1.x + f1.y;
        }
        sum0 += __shfl_xor_sync(0xffffffffu, sum0, 1);
        sum0 += __shfl_xor_sync(0xffffffffu, sum0, 2);
        sum1 += __shfl_xor_sync(0xffffffffu, sum1, 1);
        sum1 += __shfl_xor_sync(0xffffffffu, sum1, 2);
        l0 = l0 * cr0 + sum0;
        l1 = l1 * cr1 + sum1;

        // ---- rescale O ----
        #pragma unroll
        for (int dt = 0; dt < 16; dt++) {
            o[dt][0] *= cr0; o[dt][1] *= cr0;
            o[dt][2] *= cr1; o[dt][3] *= cr1;
        }

        // ---- O += P V: P accumulators ARE the A-fragments ----
        #pragma unroll
        for (int kt = 0; kt < 4; kt++) {
            uint32_t pa[4];
            pa[0] = ph0[2 * kt];
            pa[1] = ph1[2 * kt];
            pa[2] = ph0[2 * kt + 1];
            pa[3] = ph1[2 * kt + 1];
            #pragma unroll
            for (int dt = 0; dt < 16; dt++) {
                const __half* vp = sVt + (dt * 8 + g) * SVT_STRIDE + kt * 16 + 2 * t;
                uint32_t b0 = *reinterpret_cast<const uint32_t*>(vp);
                uint32_t b1 = *reinterpret_cast<const uint32_t*>(vp + 8);
                mma16816(o[dt], pa, b0, b1);
            }
        }
    }

    // ---- epilogue: normalize, round through fp16, store fp32 ----
    {
        const float il0 = 1.0f / l0;
        const float il1 = 1.0f / l1;
        const size_t r0 = (size_t)q0 + wid * 16 + g;
        float* out0 = Og + ((size_t)b * SEQL + r0)     * (NH * HD) + gl * HD;
        float* out1 = Og + ((size_t)b * SEQL + r0 + 8) * (NH * HD) + gl * HD;
        #pragma unroll
        for (int dt = 0; dt < 16; dt++) {
            const int d = dt * 8 + 2 * t;
            float2 v0, v1;
            v0.x = __half2float(__float2half(o[dt][0] * il0));
            v0.y = __half2float(__float2half(o[dt][1] * il0));
            v1.x = __half2float(__float2half(o[dt][2] * il1));
            v1.y = __half2float(__float2half(o[dt][3] * il1));
            *reinterpret_cast<float2*>(out0 + d) = v0;
            *reinterpret_cast<float2*>(out1 + d) = v1;
        }
    }
}

extern "C" void kernel_launch(void* const* d_in, const int* in_sizes, int n_in,
                              void* d_out, int out_size)
{
    const float* Q = (const float*)d_in[0];
    const float* K = (const float*)d_in[1];
    const float* V = (const float*)d_in[2];
    float* O = (float*)d_out;

    const int smem_bytes =
        (BN * SK_STRIDE + HD * SVT_STRIDE) * (int)sizeof(__half);

    cudaFuncSetAttribute(attn_fa2_kernel,
                         cudaFuncAttributeMaxDynamicSharedMemorySize, smem_bytes);

    dim3 grid(SEQL / BM, BATCH * NH);
    attn_fa2_kernel<<<grid, NTHREADS, smem_bytes>>>(Q, K, V, O);
}

// round 6
// speedup vs baseline: 9.8627x; 1.5675x over previous
#include <cuda_runtime.h>
#include <cuda_fp16.h>
#include <cstdint>

#define BATCH 2
#define SEQL  2048
#define NH    32
#define NKV   8
#define HD    128
#define KVD   512            // distinct KV rows per pseudo-batch

#define BM 128               // query rows per CTA
#define BN 64                // kv rows per tile
#define NTILES (KVD / BN)    // 8
#define NTHREADS 256

#define SK_STRIDE  136       // halves per K-tile row
#define SVT_STRIDE 72        // halves per Vt row

__device__ __forceinline__ uint32_t pack_h2(float a, float b) {
    __half2 h = __floats2half2_rn(a, b);
    return *reinterpret_cast<uint32_t*>(&h);
}

__device__ __forceinline__ void mma16816(float c[4], const uint32_t a[4],
                                         uint32_t b0, uint32_t b1) {
    asm volatile(
        "mma.sync.aligned.m16n8k16.row.col.f32.f16.f16.f32 "
        "{%0,%1,%2,%3}, {%4,%5,%6,%7}, {%8,%9}, {%0,%1,%2,%3};\n"
        : "+f"(c[0]), "+f"(c[1]), "+f"(c[2]), "+f"(c[3])
        : "r"(a[0]), "r"(a[1]), "r"(a[2]), "r"(a[3]), "r"(b0), "r"(b1));
}

// exp on the FMA pipe: exp(x) = 2^(x*log2e), deg-5 poly, rel err ~2e-6
__device__ __forceinline__ float fast_exp(float x) {
    float y = x * 1.4426950408889634f;
    y = fmaxf(y, -126.0f);
    float t  = y + 12582912.0f;
    float ri = t - 12582912.0f;
    float f  = y - ri;
    int iexp = __float_as_int(t) - 0x4B400000;
    float scale = __int_as_float((iexp + 127) << 23);
    float p = 0.0013333558f;
    p = fmaf(p, f, 0.0096181291f);
    p = fmaf(p, f, 0.0555041087f);
    p = fmaf(p, f, 0.2402265069f);
    p = fmaf(p, f, 0.6931471806f);
    p = fmaf(p, f, 1.0f);
    return p * scale;
}

__global__ __launch_bounds__(NTHREADS, 1)
void attn_fa2p_kernel(const float* __restrict__ Qg,
                      const float* __restrict__ Kg,
                      const float* __restrict__ Vg,
                      float* __restrict__ Og)
{
    extern __shared__ char smem_raw[];
    __half* sK0  = reinterpret_cast<__half*>(smem_raw);       // 2 x BN x SK_STRIDE
    __half* sVt0 = sK0 + 2 * BN * SK_STRIDE;                  // 2 x HD x SVT_STRIDE

    const int pb = blockIdx.y;           // pseudo-batch = b*32 + gl
    const int b  = pb >> 5;
    const int gl = pb & 31;
    const int q0 = blockIdx.x * BM;
    const int tid  = threadIdx.x;
    const int wid  = tid >> 5;
    const int lane = tid & 31;
    const int g = lane >> 2;
    const int t = lane & 3;

    const size_t qbase  = ((size_t)b * SEQL + (size_t)gl * 64) * NH  * HD;
    const size_t kvbase = ((size_t)b * SEQL + (size_t)gl * 64) * NKV * HD;

    const __half hscale = __float2half(0.08838834764831845f);

    // ---- Q A-fragments in registers (fp32 -> fp16) ----
    uint32_t qa[8][4];
    {
        const float* q_r0 = Qg + qbase + (size_t)(q0 + wid * 16 + g) * HD;
        const float* q_r8 = q_r0 + 8 * HD;
        #pragma unroll
        for (int kt = 0; kt < 8; kt++) {
            const int c0 = kt * 16 + t * 2;
            float2 a0 = *reinterpret_cast<const float2*>(q_r0 + c0);
            float2 a1 = *reinterpret_cast<const float2*>(q_r8 + c0);
            float2 a2 = *reinterpret_cast<const float2*>(q_r0 + c0 + 8);
            float2 a3 = *reinterpret_cast<const float2*>(q_r8 + c0 + 8);
            qa[kt][0] = pack_h2(a0.x, a0.y);
            qa[kt][1] = pack_h2(a1.x, a1.y);
            qa[kt][2] = pack_h2(a2.x, a2.y);
            qa[kt][3] = pack_h2(a3.x, a3.y);
        }
    }

    // per-thread load geometry (fixed across tiles)
    const float* kp_base = Kg + kvbase + (size_t)wid * HD + (lane * 4);
    const float* vp_base = Vg + kvbase + (size_t)(2 * lane) * HD + wid * 4;

    float4 kreg[8];   // K rows wid+8j, cols lane*4..+3
    float4 vreg[8];   // V pairs (2*lane, 2*lane+1), d-block wid+8j (j<4), 2 regs each

    // ---- prologue: fetch tile 0 ----
    #pragma unroll
    for (int j = 0; j < 8; j++)
        kreg[j] = *reinterpret_cast<const float4*>(kp_base + (size_t)(8 * j) * HD);
    #pragma unroll
    for (int j = 0; j < 4; j++) {
        const float* vp = vp_base + 8 * j * 4;
        vreg[2 * j]     = *reinterpret_cast<const float4*>(vp);
        vreg[2 * j + 1] = *reinterpret_cast<const float4*>(vp + HD);
    }

    float m0 = -1e30f, m1 = -1e30f;
    float l0 = 0.0f,   l1 = 0.0f;

    float o[16][4];
    #pragma unroll
    for (int d = 0; d < 16; d++)
        #pragma unroll
        for (int j = 0; j < 4; j++) o[d][j] = 0.0f;

    for (int it = 0; it < NTILES; it++) {
        __half* sK  = sK0  + (it & 1) * BN * SK_STRIDE;
        __half* sVt = sVt0 + (it & 1) * HD * SVT_STRIDE;

        // ---- store staged tile (convert fp32->fp16, V transposed) ----
        #pragma unroll
        for (int j = 0; j < 8; j++) {
            uint2 packed;
            packed.x = pack_h2(kreg[j].x, kreg[j].y);
            packed.y = pack_h2(kreg[j].z, kreg[j].w);
            *reinterpret_cast<uint2*>(sK + (wid + 8 * j) * SK_STRIDE + lane * 4) = packed;
        }
        #pragma unroll
        for (int j = 0; j < 4; j++) {
            const int c4 = wid + 8 * j;
            const float* pa  = &vreg[2 * j].x;
            const float* pbv = &vreg[2 * j + 1].x;
            #pragma unroll
            for (int e = 0; e < 4; e++) {
                *reinterpret_cast<uint32_t*>(sVt + (c4 * 4 + e) * SVT_STRIDE + 2 * lane)
                    = pack_h2(pa[e], pbv[e]);
            }
        }
        __syncthreads();

        // ---- issue next tile's global loads (latency hidden under compute) ----
        if (it + 1 < NTILES) {
            const size_t off = (size_t)(it + 1) * BN * HD;
            #pragma unroll
            for (int j = 0; j < 8; j++)
                kreg[j] = *reinterpret_cast<const float4*>(
                    kp_base + off + (size_t)(8 * j) * HD);
            #pragma unroll
            for (int j = 0; j < 4; j++) {
                const float* vp = vp_base + off + 8 * j * 4;
                vreg[2 * j]     = *reinterpret_cast<const float4*>(vp);
                vreg[2 * j + 1] = *reinterpret_cast<const float4*>(vp + HD);
            }
        }

        // ---- S = Q K^T (HMMA), in registers ----
        float sc[8][4];
        #pragma unroll
        for (int nt = 0; nt < 8; nt++)
            #pragma unroll
            for (int j = 0; j < 4; j++) sc[nt][j] = 0.0f;

        #pragma unroll
        for (int kt = 0; kt < 8; kt++) {
            #pragma unroll
            for (int nt = 0; nt < 8; nt++) {
                const __half* kp = sK + (nt * 8 + g) * SK_STRIDE + kt * 16 + 2 * t;
                uint32_t b0 = *reinterpret_cast<const uint32_t*>(kp);
                uint32_t b1 = *reinterpret_cast<const uint32_t*>(kp + 8);
                mma16816(sc[nt], qa[kt], b0, b1);
            }
        }

        // ---- reference-exact double fp16 rounding of S ----
        #pragma unroll
        for (int nt = 0; nt < 8; nt++)
            #pragma unroll
            for (int j = 0; j < 4; j++)
                sc[nt][j] = __half2float(__hmul(__float2half(sc[nt][j]), hscale));

        // ---- register softmax ----
        float tm0 = -1e30f, tm1 = -1e30f;
        #pragma unroll
        for (int nt = 0; nt < 8; nt++) {
            tm0 = fmaxf(tm0, fmaxf(sc[nt][0], sc[nt][1]));
            tm1 = fmaxf(tm1, fmaxf(sc[nt][2], sc[nt][3]));
        }
        tm0 = fmaxf(tm0, __shfl_xor_sync(0xffffffffu, tm0, 1));
        tm0 = fmaxf(tm0, __shfl_xor_sync(0xffffffffu, tm0, 2));
        tm1 = fmaxf(tm1, __shfl_xor_sync(0xffffffffu, tm1, 1));
        tm1 = fmaxf(tm1, __shfl_xor_sync(0xffffffffu, tm1, 2));

        const float mn0 = fmaxf(m0, tm0);
        const float mn1 = fmaxf(m1, tm1);
        const float cr0 = fast_exp(m0 - mn0);
        const float cr1 = fast_exp(m1 - mn1);
        m0 = mn0; m1 = mn1;

        uint32_t ph0[8], ph1[8];
        float sum0 = 0.0f, sum1 = 0.0f;
        #pragma unroll
        for (int nt = 0; nt < 8; nt++) {
            __half2 h0 = __floats2half2_rn(fast_exp(sc[nt][0] - mn0),
                                           fast_exp(sc[nt][1] - mn0));
            __half2 h1 = __floats2half2_rn(fast_exp(sc[nt][2] - mn1),
                                           fast_exp(sc[nt][3] - mn1));
            ph0[nt] = *reinterpret_cast<uint32_t*>(&h0);
            ph1[nt] = *reinterpret_cast<uint32_t*>(&h1);
            float2 f0 = __half22float2(h0);
            float2 f1 = __half22float2(h1);
            sum0 += f0.x + f0.y;
            sum1 += f1.x + f1.y;
        }
        sum0 += __shfl_xor_sync(0xffffffffu, sum0, 1);
        sum0 += __shfl_xor_sync(0xffffffffu, sum0, 2);
        sum1 += __shfl_xor_sync(0xffffffffu, sum1, 1);
        sum1 += __shfl_xor_sync(0xffffffffu, sum1, 2);
        l0 = l0 * cr0 + sum0;
        l1 = l1 * cr1 + sum1;

        // ---- rescale O ----
        #pragma unroll
        for (int dt = 0; dt < 16; dt++) {
            o[dt][0] *= cr0; o[dt][1] *= cr0;
            o[dt][2] *= cr1; o[dt][3] *= cr1;
        }

        // ---- O += P V: P accumulators ARE the A-fragments ----
        #pragma unroll
        for (int kt = 0; kt < 4; kt++) {
            uint32_t pa[4];
            pa[0] = ph0[2 * kt];
            pa[1] = ph1[2 * kt];
            pa[2] = ph0[2 * kt + 1];
            pa[3] = ph1[2 * kt + 1];
            #pragma unroll
            for (int dt = 0; dt < 16; dt++) {
                const __half* vp = sVt + (dt * 8 + g) * SVT_STRIDE + kt * 16 + 2 * t;
                uint32_t b0 = *reinterpret_cast<const uint32_t*>(vp);
                uint32_t b1 = *reinterpret_cast<const uint32_t*>(vp + 8);
                mma16816(o[dt], pa, b0, b1);
            }
        }
    }

    // ---- epilogue: normalize, round through fp16, store fp32 ----
    {
        const float il0 = 1.0f / l0;
        const float il1 = 1.0f / l1;
        const size_t r0 = (size_t)q0 + wid * 16 + g;
        float* out0 = Og + ((size_t)b * SEQL + r0)     * (NH * HD) + gl * HD;
        float* out1 = Og + ((size_t)b * SEQL + r0 + 8) * (NH * HD) + gl * HD;
        #pragma unroll
        for (int dt = 0; dt < 16; dt++) {
            const int d = dt * 8 + 2 * t;
            float2 v0, v1;
            v0.x = __half2float(__float2half(o[dt][0] * il0));
            v0.y = __half2float(__float2half(o[dt][1] * il0));
            v1.x = __half2float(__float2half(o[dt][2] * il1));
            v1.y = __half2float(__float2half(o[dt][3] * il1));
            *reinterpret_cast<float2*>(out0 + d) = v0;
            *reinterpret_cast<float2*>(out1 + d) = v1;
        }
    }
}

extern "C" void kernel_launch(void* const* d_in, const int* in_sizes, int n_in,
                              void* d_out, int out_size)
{
    const float* Q = (const float*)d_in[0];
    const float* K = (const float*)d_in[1];
    const float* V = (const float*)d_in[2];
    float* O = (float*)d_out;

    const int smem_bytes =
        2 * (BN * SK_STRIDE + HD * SVT_STRIDE) * (int)sizeof(__half);

    cudaFuncSetAttribute(attn_fa2p_kernel,
                         cudaFuncAttributeMaxDynamicSharedMemorySize, smem_bytes);

    dim3 grid(SEQL / BM, BATCH * NH);
    attn_fa2p_kernel<<<grid, NTHREADS, smem_bytes>>>(Q, K, V, O);
}